// round 1
// baseline (speedup 1.0000x reference)
#include <cuda_runtime.h>
#include <math.h>

#define NH 4
#define KD 32
#define LSEQ 4096

// Scratch (allocation-free rule: __device__ globals)
__device__ float g_Q[2 * NH * LSEQ * KD];   // unscaled q, [b][n][l][d]
__device__ float g_K[2 * NH * LSEQ * KD];   // k * 1/sqrt(kd)
__device__ float g_V[2 * NH * LSEQ * KD];

// ---------------------------------------------------------------------------
// QKV projection: x[8192,128] @ w[128,384], scatter into g_Q/g_K/g_V.
// Block tile 64x128, BK=32. 256 threads, 4x8 micro-tile per thread.
// ---------------------------------------------------------------------------
__global__ __launch_bounds__(256) void qkv_kernel(const float* __restrict__ x,
                                                  const float* __restrict__ w) {
    __shared__ float As[64][36];     // [row][k] padded
    __shared__ float Bs[32][128];    // [k][col]
    const int n0 = blockIdx.x * 128;
    const int m0 = blockIdx.y * 64;
    const int tid = threadIdx.x;
    const int ty = tid >> 4, tx = tid & 15;

    float acc[4][8];
#pragma unroll
    for (int i = 0; i < 4; i++)
#pragma unroll
        for (int j = 0; j < 8; j++) acc[i][j] = 0.f;

    for (int kb = 0; kb < 4; kb++) {
#pragma unroll
        for (int r8 = 0; r8 < 2; r8++) {
            int f = tid + 256 * r8;           // [0,512)
            int r = f >> 3, k4 = f & 7;
            float4 v = *reinterpret_cast<const float4*>(
                &x[(size_t)(m0 + r) * 128 + kb * 32 + 4 * k4]);
            *reinterpret_cast<float4*>(&As[r][4 * k4]) = v;
        }
#pragma unroll
        for (int r8 = 0; r8 < 4; r8++) {
            int f = tid + 256 * r8;           // [0,1024)
            int kk = f >> 5, c4 = f & 31;
            float4 v = *reinterpret_cast<const float4*>(
                &w[(size_t)(kb * 32 + kk) * 384 + n0 + 4 * c4]);
            *reinterpret_cast<float4*>(&Bs[kk][4 * c4]) = v;
        }
        __syncthreads();
#pragma unroll
        for (int kk = 0; kk < 32; kk++) {
            float a[4], b[8];
#pragma unroll
            for (int i = 0; i < 4; i++) a[i] = As[4 * ty + i][kk];
#pragma unroll
            for (int j = 0; j < 8; j++) b[j] = Bs[kk][tx + 16 * j];
#pragma unroll
            for (int i = 0; i < 4; i++)
#pragma unroll
                for (int j = 0; j < 8; j++) acc[i][j] = fmaf(a[i], b[j], acc[i][j]);
        }
        __syncthreads();
    }

    const float scale = 0.17677669529663688f;  // 1/sqrt(32)
#pragma unroll
    for (int i = 0; i < 4; i++) {
        int m = m0 + 4 * ty + i;
        int b = m >> 12, l = m & 4095;
#pragma unroll
        for (int j = 0; j < 8; j++) {
            int c = n0 + tx + 16 * j;
            float v = acc[i][j];
            if (c < 128) {
                int n = c >> 5, d = c & 31;
                g_Q[(((size_t)(b * NH + n)) * LSEQ + l) * KD + d] = v;
            } else if (c < 256) {
                int cc = c - 128, n = cc >> 5, d = cc & 31;
                g_K[(((size_t)(b * NH + n)) * LSEQ + l) * KD + d] = v * scale;
            } else {
                int cc = c - 256, n = cc >> 5, d = cc & 31;
                g_V[(((size_t)(b * NH + n)) * LSEQ + l) * KD + d] = v;
            }
        }
    }
}

// ---------------------------------------------------------------------------
// Flash attention with decomposed relative-position bias.
// Block = (query row qi, batch*head bn). 64 queries/block, 64-key tiles.
// S[qj,kj] = Q·Kscaled^T + BH[qj][ki] + BW[qj][kj]; online softmax; O += P·V.
// Thread map: 16x16; thread(ty,tx) owns q rows {4ty+i}, k cols {tx+16j},
// and O cols dv {2tx, 2tx+1}.
// ---------------------------------------------------------------------------
#define ATTN_SMEM_FLOATS (64 * 36 + 64 * 64 + 64 * 64 + 8960)
#define ATTN_SMEM_BYTES (ATTN_SMEM_FLOATS * 4)

__global__ __launch_bounds__(256) void attn_kernel(const float* __restrict__ peh,
                                                   const float* __restrict__ pew,
                                                   float* __restrict__ out) {
    extern __shared__ float sm[];
    float* Qs = sm;                  // 64*36
    float* BW = Qs + 64 * 36;        // 64*64
    float* BH = BW + 64 * 64;        // 64*64
    float* X = BH + 64 * 64;         // 8960 floats, phase-overlaid
    float* Ph = X;                   // phase 1: 127*32
    float* Pw = X + 127 * 32;        // phase 1: 127*32
    float* Ks = X;                   // phase 2: 64*36
    float* Vs = Ks + 64 * 36;        // phase 2: 64*36
    float* Ps = Vs + 64 * 36;        // phase 2: 64*68

    const int qi = blockIdx.x;   // query row, 0..63
    const int bn = blockIdx.y;   // b*NH+n, 0..7
    const int tid = threadIdx.x;
    const int ty = tid >> 4, tx = tid & 15;

    const float* Qg = g_Q + ((size_t)bn * LSEQ + qi * 64) * KD;
    const float* Kg = g_K + (size_t)bn * LSEQ * KD;
    const float* Vg = g_V + (size_t)bn * LSEQ * KD;

    // Load Q tile (contiguous 8KB) into Qs[q][d] padded rows
#pragma unroll
    for (int r8 = 0; r8 < 2; r8++) {
        int f = tid + 256 * r8;
        int q = f >> 3, d4 = f & 7;
        float4 v = *reinterpret_cast<const float4*>(&Qg[q * 32 + 4 * d4]);
        *reinterpret_cast<float4*>(&Qs[q * 36 + 4 * d4]) = v;
    }
    // Load relative position tables (127x32 each) into smem
    for (int f = tid; f < 1016; f += 256) {
        *reinterpret_cast<float4*>(&Ph[f * 4]) =
            *reinterpret_cast<const float4*>(&peh[f * 4]);
        *reinterpret_cast<float4*>(&Pw[f * 4]) =
            *reinterpret_cast<const float4*>(&pew[f * 4]);
    }
    __syncthreads();

    // Bias precompute: BW[qj][kj] = Q[qj]·pos_w[kj-qj+63];
    //                  BH[qj][ki] = Q[qj]·pos_h[ki-qi+63]
    for (int idx = tid; idx < 8192; idx += 256) {
        int which = idx >> 12;           // 0 -> BW, 1 -> BH
        int q = (idx >> 6) & 63;
        int kc = idx & 63;
        const float* emb = which ? &Ph[(kc - qi + 63) * 32] : &Pw[(kc - q + 63) * 32];
        const float* qrow = &Qs[q * 36];
        float s = 0.f;
#pragma unroll
        for (int d4 = 0; d4 < 8; d4++) {
            float4 a = *reinterpret_cast<const float4*>(&qrow[4 * d4]);
            float4 b = *reinterpret_cast<const float4*>(&emb[4 * d4]);
            s += a.x * b.x + a.y * b.y + a.z * b.z + a.w * b.w;
        }
        (which ? BH : BW)[q * 64 + kc] = s;
    }
    __syncthreads();

    float m_old[4], lsum[4], O[4][2];
#pragma unroll
    for (int i = 0; i < 4; i++) {
        m_old[i] = -1e30f;
        lsum[i] = 0.f;
        O[i][0] = 0.f;
        O[i][1] = 0.f;
    }

    for (int kt = 0; kt < 64; kt++) {
        // Load K/V tiles (contiguous 8KB each)
#pragma unroll
        for (int r8 = 0; r8 < 2; r8++) {
            int f = tid + 256 * r8;
            int k = f >> 3, d4 = f & 7;
            float4 kv = *reinterpret_cast<const float4*>(&Kg[(kt * 64 + k) * 32 + 4 * d4]);
            float4 vv = *reinterpret_cast<const float4*>(&Vg[(kt * 64 + k) * 32 + 4 * d4]);
            *reinterpret_cast<float4*>(&Ks[k * 36 + 4 * d4]) = kv;
            *reinterpret_cast<float4*>(&Vs[k * 36 + 4 * d4]) = vv;
        }
        __syncthreads();

        // S = bias + Q K^T (k already scaled)
        float s[4][4];
#pragma unroll
        for (int i = 0; i < 4; i++) {
            float bh = BH[(4 * ty + i) * 64 + kt];
#pragma unroll
            for (int j = 0; j < 4; j++)
                s[i][j] = bh + BW[(4 * ty + i) * 64 + tx + 16 * j];
        }
#pragma unroll
        for (int d4 = 0; d4 < 8; d4++) {
            float4 qv[4], kv[4];
#pragma unroll
            for (int i = 0; i < 4; i++)
                qv[i] = *reinterpret_cast<const float4*>(&Qs[(4 * ty + i) * 36 + 4 * d4]);
#pragma unroll
            for (int j = 0; j < 4; j++)
                kv[j] = *reinterpret_cast<const float4*>(&Ks[(tx + 16 * j) * 36 + 4 * d4]);
#pragma unroll
            for (int i = 0; i < 4; i++)
#pragma unroll
                for (int j = 0; j < 4; j++) {
                    s[i][j] = fmaf(qv[i].x, kv[j].x, s[i][j]);
                    s[i][j] = fmaf(qv[i].y, kv[j].y, s[i][j]);
                    s[i][j] = fmaf(qv[i].z, kv[j].z, s[i][j]);
                    s[i][j] = fmaf(qv[i].w, kv[j].w, s[i][j]);
                }
        }

        // Online softmax per q row; reduce over tx (16-lane groups)
#pragma unroll
        for (int i = 0; i < 4; i++) {
            float mx = fmaxf(fmaxf(s[i][0], s[i][1]), fmaxf(s[i][2], s[i][3]));
#pragma unroll
            for (int m = 1; m < 16; m <<= 1)
                mx = fmaxf(mx, __shfl_xor_sync(0xffffffffu, mx, m, 16));
            float m_new = fmaxf(m_old[i], mx);
            float corr = __expf(m_old[i] - m_new);
            float rs = 0.f;
#pragma unroll
            for (int j = 0; j < 4; j++) {
                s[i][j] = __expf(s[i][j] - m_new);
                rs += s[i][j];
            }
#pragma unroll
            for (int m = 1; m < 16; m <<= 1)
                rs += __shfl_xor_sync(0xffffffffu, rs, m, 16);
            lsum[i] = lsum[i] * corr + rs;
            O[i][0] *= corr;
            O[i][1] *= corr;
            m_old[i] = m_new;
        }

        // Store P (conflict-free STS.32: banks = tx + 16*(ty&1) + c, all distinct)
#pragma unroll
        for (int i = 0; i < 4; i++)
#pragma unroll
            for (int j = 0; j < 4; j++)
                Ps[(4 * ty + i) * 68 + tx + 16 * j] = s[i][j];
        __syncthreads();

        // O += P·V  (P rows via broadcast float4 loads; V via float2)
#pragma unroll
        for (int k4 = 0; k4 < 16; k4++) {
            float4 p[4];
#pragma unroll
            for (int i = 0; i < 4; i++)
                p[i] = *reinterpret_cast<const float4*>(&Ps[(4 * ty + i) * 68 + 4 * k4]);
#pragma unroll
            for (int kk = 0; kk < 4; kk++) {
                float2 vv = *reinterpret_cast<const float2*>(&Vs[(4 * k4 + kk) * 36 + 2 * tx]);
#pragma unroll
                for (int i = 0; i < 4; i++) {
                    float pk = reinterpret_cast<const float*>(&p[i])[kk];
                    O[i][0] = fmaf(pk, vv.x, O[i][0]);
                    O[i][1] = fmaf(pk, vv.y, O[i][1]);
                }
            }
        }
        __syncthreads();  // Ks/Vs/Ps reused next iteration
    }

    // Epilogue: out[b][l][n*32 + dv] = O / lsum
    const int b = bn >> 2, n = bn & 3;
#pragma unroll
    for (int i = 0; i < 4; i++) {
        int l = qi * 64 + 4 * ty + i;
        float inv = 1.f / lsum[i];
        float2 o;
        o.x = O[i][0] * inv;
        o.y = O[i][1] * inv;
        *reinterpret_cast<float2*>(&out[((size_t)b * LSEQ + l) * 128 + n * 32 + 2 * tx]) = o;
    }
}

// ---------------------------------------------------------------------------
extern "C" void kernel_launch(void* const* d_in, const int* in_sizes, int n_in,
                              void* d_out, int out_size) {
    const float* x = (const float*)d_in[0];      // [2,64,64,128]
    const float* w = (const float*)d_in[1];      // [128,384]
    const float* peh = (const float*)d_in[2];    // [127,32]
    const float* pew = (const float*)d_in[3];    // [127,32]
    float* out = (float*)d_out;                  // [2,64,64,128] fp32

    // Idempotent; also takes effect on the (uncaptured) correctness call.
    cudaFuncSetAttribute(attn_kernel, cudaFuncAttributeMaxDynamicSharedMemorySize,
                         ATTN_SMEM_BYTES);

    qkv_kernel<<<dim3(3, 128), 256>>>(x, w);
    attn_kernel<<<dim3(64, 8), 256, ATTN_SMEM_BYTES>>>(peh, pew, out);
}